// round 1
// baseline (speedup 1.0000x reference)
#include <cuda_runtime.h>
#include <cuda_bf16.h>

// Problem constants (verified against reference: N=100000, E=1600000,
// IN_C=16, HID=32, HEADS=2, TEMP=0.7, NEG_SLOPE=0.2)
#define MAXN 100000
#define NEG 0.2f
#define INV_TEMP (1.0f / 0.7f)

// ---- device scratch (static; no allocations allowed) ----
__device__ __align__(16) float g_xp[MAXN * 64];    // [N][H=2][C=32] projected features
__device__ __align__(16) float g_num[MAXN * 64];   // softmax-weighted message numerator
__device__ float g_asrc[MAXN * 2];                 // attention src logits per head
__device__ float g_adst[MAXN * 2];                 // attention dst logits per head
__device__ float g_denom[MAXN * 2];                // softmax denominators per head
__device__ __align__(16) float g_ps[MAXN * 32];    // h_node @ w1[0:32,:]
__device__ __align__(16) float g_pd[MAXN * 32];    // h_node @ w1[32:64,:]
__device__ int g_is64;                             // edge_index element width flag

// vectorized float reduction to global (sm_90+)
__device__ __forceinline__ void red_add_v4(float* p, float a, float b, float c, float d) {
    asm volatile("red.global.add.v4.f32 [%0], {%1,%2,%3,%4};"
                 :: "l"(p), "f"(a), "f"(b), "f"(c), "f"(d) : "memory");
}

// edge index fetch that works for both int64 and int32 storage
__device__ __forceinline__ void load_edge(const void* ei, int e, int E, int is64,
                                          int& s, int& d) {
    if (is64) {
        const long long* p = (const long long*)ei;
        s = (int)p[e];
        d = (int)p[e + E];
    } else {
        const int* p = (const int*)ei;
        s = p[e];
        d = p[e + E];
    }
}

// K0: detect whether edge_index is stored as int64 or int32.
// Values are node ids < 2^31, so if data is int64, the high 32-bit word of
// every element is 0. Probability of 64 consecutive int32 values being 0 is ~0.
__global__ void k0_detect(const int* ei_words) {
    if (threadIdx.x == 0 && blockIdx.x == 0) {
        int nonzero = 0;
        #pragma unroll
        for (int i = 0; i < 64; i++)
            if (ei_words[2 * i + 1] != 0) nonzero++;
        g_is64 = (nonzero == 0) ? 1 : 0;
    }
}

// K1: per-node: xp = x@W, attention logits, self-loop init of num/denom.
__global__ void k1_node(const float* __restrict__ x, const float* __restrict__ W,
                        const float* __restrict__ att_src, const float* __restrict__ att_dst,
                        int N) {
    __shared__ float sW[16 * 64];
    __shared__ float sAs[64];
    __shared__ float sAd[64];
    int tid = threadIdx.x;
    for (int i = tid; i < 16 * 64; i += blockDim.x) sW[i] = W[i];
    if (tid < 64) { sAs[tid] = att_src[tid]; sAd[tid] = att_dst[tid]; }
    __syncthreads();

    int n = blockIdx.x * blockDim.x + tid;
    if (n >= N) return;

    float xv[16];
    const float4* x4 = (const float4*)(x + (size_t)n * 16);
    #pragma unroll
    for (int i = 0; i < 4; i++) {
        float4 t = x4[i];
        xv[4 * i + 0] = t.x; xv[4 * i + 1] = t.y;
        xv[4 * i + 2] = t.z; xv[4 * i + 3] = t.w;
    }

    float xp[64];
    float a0s = 0.f, a1s = 0.f, a0d = 0.f, a1d = 0.f;
    #pragma unroll
    for (int j = 0; j < 64; j++) {
        float v = 0.f;
        #pragma unroll
        for (int k = 0; k < 16; k++) v = fmaf(xv[k], sW[k * 64 + j], v);
        xp[j] = v;
        float as = sAs[j] * v;
        float ad = sAd[j] * v;
        if (j < 32) { a0s += as; a0d += ad; }
        else        { a1s += as; a1d += ad; }
    }

    g_asrc[n * 2 + 0] = a0s; g_asrc[n * 2 + 1] = a1s;
    g_adst[n * 2 + 0] = a0d; g_adst[n * 2 + 1] = a1d;

    // self-loop contribution (src = dst = n)
    float e0 = a0s + a0d; e0 = e0 > 0.f ? e0 : NEG * e0;
    float e1 = a1s + a1d; e1 = e1 > 0.f ? e1 : NEG * e1;
    float w0 = __expf(e0);
    float w1h = __expf(e1);
    g_denom[n * 2 + 0] = w0;
    g_denom[n * 2 + 1] = w1h;

    float4* xpo  = (float4*)(g_xp  + (size_t)n * 64);
    float4* numo = (float4*)(g_num + (size_t)n * 64);
    #pragma unroll
    for (int q = 0; q < 16; q++) {
        float w = (q < 8) ? w0 : w1h;
        float4 t = make_float4(xp[4 * q], xp[4 * q + 1], xp[4 * q + 2], xp[4 * q + 3]);
        xpo[q] = t;
        numo[q] = make_float4(w * t.x, w * t.y, w * t.z, w * t.w);
    }
}

// K2: per-edge scatter. 16 lanes per edge, each handles one float4 chunk of
// the 64-float message. Softmax max-shift is skipped (shift-invariant,
// |e| < ~5 so exp cannot overflow).
__global__ void k2_edge_scatter(const void* __restrict__ ei, int E) {
    long long t = (long long)blockIdx.x * blockDim.x + threadIdx.x;
    int e = (int)(t >> 4);
    int q = (int)(t & 15);
    if (e >= E) return;
    int is64 = g_is64;
    int s, d;
    load_edge(ei, e, E, is64, s, d);

    int h = q >> 3;  // chunk q covers floats [q*4, q*4+4) -> head = q/8
    float ee = g_asrc[s * 2 + h] + g_adst[d * 2 + h];
    ee = ee > 0.f ? ee : NEG * ee;
    float w = __expf(ee);
    if ((q & 7) == 0) atomicAdd(&g_denom[d * 2 + h], w);

    float4 v = *(const float4*)(g_xp + (size_t)s * 64 + q * 4);
    red_add_v4(g_num + (size_t)d * 64 + q * 4, w * v.x, w * v.y, w * v.z, w * v.w);
}

// K3: per-node finalize: h = mean over heads of (num/denom) + bias, then fold
// MLP layer 1 into per-node partials ps = h @ w1_top, pd = h @ w1_bot.
// One warp per node; lane = output channel.
__global__ void k3_node_p(const float* __restrict__ bias, const float* __restrict__ w1,
                          int N) {
    __shared__ float sW1[64 * 32];
    int tid = threadIdx.x;
    for (int i = tid; i < 64 * 32; i += blockDim.x) sW1[i] = w1[i];
    __syncthreads();

    int gw = (blockIdx.x * blockDim.x + tid) >> 5;
    int c = tid & 31;
    bool valid = gw < N;
    int n = valid ? gw : 0;

    float d0 = g_denom[n * 2 + 0] + 1e-16f;
    float d1 = g_denom[n * 2 + 1] + 1e-16f;
    float h = 0.5f * (g_num[(size_t)n * 64 + c] / d0 +
                      g_num[(size_t)n * 64 + 32 + c] / d1) + bias[c];

    float ps = 0.f, pd = 0.f;
    #pragma unroll
    for (int k = 0; k < 32; k++) {
        float hk = __shfl_sync(0xFFFFFFFFu, h, k);
        ps = fmaf(hk, sW1[k * 32 + c], ps);
        pd = fmaf(hk, sW1[(32 + k) * 32 + c], pd);
    }
    if (valid) {
        g_ps[(size_t)n * 32 + c] = ps;
        g_pd[(size_t)n * 32 + c] = pd;
    }
}

// K4: per-edge MLP. 8 lanes per edge, each handles a float4 of the 32 hidden
// units: hidden = relu(ps[s] + pd[d] + b1); logit = hidden . w2 + b2; /TEMP.
__global__ void k4_edge_mlp(const void* __restrict__ ei,
                            const float* __restrict__ b1, const float* __restrict__ w2,
                            const float* __restrict__ b2, float* __restrict__ out, int E) {
    long long t = (long long)blockIdx.x * blockDim.x + threadIdx.x;
    int e = (int)(t >> 3);
    int q = (int)(t & 7);
    bool valid = e < E;
    int is64 = g_is64;
    int s = 0, d = 0;
    if (valid) load_edge(ei, e, E, is64, s, d);

    float4 a  = *(const float4*)(g_ps + (size_t)s * 32 + q * 4);
    float4 b  = *(const float4*)(g_pd + (size_t)d * 32 + q * 4);
    float4 bb = *(const float4*)(b1 + q * 4);
    float4 ww = *(const float4*)(w2 + q * 4);

    float h0 = fmaxf(a.x + b.x + bb.x, 0.f);
    float h1 = fmaxf(a.y + b.y + bb.y, 0.f);
    float h2 = fmaxf(a.z + b.z + bb.z, 0.f);
    float h3 = fmaxf(a.w + b.w + bb.w, 0.f);
    float acc = h0 * ww.x + h1 * ww.y + h2 * ww.z + h3 * ww.w;

    acc += __shfl_xor_sync(0xFFFFFFFFu, acc, 1);
    acc += __shfl_xor_sync(0xFFFFFFFFu, acc, 2);
    acc += __shfl_xor_sync(0xFFFFFFFFu, acc, 4);

    if (valid && q == 0) out[e] = (acc + b2[0]) * INV_TEMP;
}

extern "C" void kernel_launch(void* const* d_in, const int* in_sizes, int n_in,
                              void* d_out, int out_size) {
    const float* x        = (const float*)d_in[0];
    const void*  ei       = d_in[1];                 // int64 or int32, detected on device
    const float* W        = (const float*)d_in[2];
    const float* att_src  = (const float*)d_in[3];
    const float* att_dst  = (const float*)d_in[4];
    const float* bias     = (const float*)d_in[5];
    const float* w1       = (const float*)d_in[6];
    const float* b1       = (const float*)d_in[7];
    const float* w2       = (const float*)d_in[8];
    const float* b2       = (const float*)d_in[9];
    float* out = (float*)d_out;

    int N = in_sizes[0] / 16;  // x is [N, 16]
    int E = in_sizes[1] / 2;   // edge_index is [2, E]

    k0_detect<<<1, 32>>>((const int*)ei);
    k1_node<<<(N + 127) / 128, 128>>>(x, W, att_src, att_dst, N);
    {
        long long T = (long long)E * 16;
        k2_edge_scatter<<<(unsigned)((T + 255) / 256), 256>>>(ei, E);
    }
    {
        long long T = (long long)N * 32;
        k3_node_p<<<(unsigned)((T + 255) / 256), 256>>>(bias, w1, N);
    }
    {
        long long T = (long long)E * 8;
        k4_edge_mlp<<<(unsigned)((T + 255) / 256), 256>>>(ei, b1, w2, b2, out, E);
    }
}

// round 2
// speedup vs baseline: 1.2091x; 1.2091x over previous
#include <cuda_runtime.h>
#include <cuda_fp16.h>

// Problem constants: N=100000, E=1600000, IN_C=16, HID=32, HEADS=2
#define MAXN 100000
#define NEG 0.2f
#define INV_TEMP (1.0f / 0.7f)

// ---- device scratch (static; no allocations allowed) ----
__device__ __align__(16) __half g_xp[MAXN * 64];   // [N][64] projected features (fp16)
__device__ __align__(16) float g_num[MAXN * 64];   // softmax-weighted message numerator (fp32)
__device__ float g_asrc[MAXN * 2];                 // attention src logits per head
__device__ float g_adst[MAXN * 2];                 // attention dst logits per head
__device__ float g_denom[MAXN * 2];                // softmax denominators per head
__device__ __align__(16) __half g_ps[MAXN * 32];   // h_node @ w1[0:32,:]  (fp16)
__device__ __align__(16) __half g_pd[MAXN * 32];   // h_node @ w1[32:64,:] (fp16)
__device__ __align__(16) int2 g_edge[1600000];     // packed (src, dst) int32
__device__ int g_is64;                             // edge_index element width flag

// vectorized float reduction to global (sm_90+)
__device__ __forceinline__ void red_add_v4(float* p, float a, float b, float c, float d) {
    asm volatile("red.global.add.v4.f32 [%0], {%1,%2,%3,%4};"
                 :: "l"(p), "f"(a), "f"(b), "f"(c), "f"(d) : "memory");
}

// K0: detect whether edge_index is stored as int64 or int32.
__global__ void k0_detect(const int* ei_words) {
    if (threadIdx.x == 0 && blockIdx.x == 0) {
        int nonzero = 0;
        #pragma unroll
        for (int i = 0; i < 64; i++)
            if (ei_words[2 * i + 1] != 0) nonzero++;
        g_is64 = (nonzero == 0) ? 1 : 0;
    }
}

// K0b: pack edge index into int2 (src, dst)
__global__ void k0_pack(const void* __restrict__ ei, int E) {
    int e = blockIdx.x * blockDim.x + threadIdx.x;
    if (e >= E) return;
    int s, d;
    if (g_is64) {
        const long long* p = (const long long*)ei;
        s = (int)p[e];
        d = (int)p[e + E];
    } else {
        const int* p = (const int*)ei;
        s = p[e];
        d = p[e + E];
    }
    g_edge[e] = make_int2(s, d);
}

// K1: per-node: xp = x@W, attention logits, self-loop init of num/denom.
__global__ void k1_node(const float* __restrict__ x, const float* __restrict__ W,
                        const float* __restrict__ att_src, const float* __restrict__ att_dst,
                        int N) {
    __shared__ float sW[16 * 64];
    __shared__ float sAs[64];
    __shared__ float sAd[64];
    int tid = threadIdx.x;
    for (int i = tid; i < 16 * 64; i += blockDim.x) sW[i] = W[i];
    if (tid < 64) { sAs[tid] = att_src[tid]; sAd[tid] = att_dst[tid]; }
    __syncthreads();

    int n = blockIdx.x * blockDim.x + tid;
    if (n >= N) return;

    float xv[16];
    const float4* x4 = (const float4*)(x + (size_t)n * 16);
    #pragma unroll
    for (int i = 0; i < 4; i++) {
        float4 t = x4[i];
        xv[4 * i + 0] = t.x; xv[4 * i + 1] = t.y;
        xv[4 * i + 2] = t.z; xv[4 * i + 3] = t.w;
    }

    float xp[64];
    float a0s = 0.f, a1s = 0.f, a0d = 0.f, a1d = 0.f;
    #pragma unroll
    for (int j = 0; j < 64; j++) {
        float v = 0.f;
        #pragma unroll
        for (int k = 0; k < 16; k++) v = fmaf(xv[k], sW[k * 64 + j], v);
        xp[j] = v;
        float as = sAs[j] * v;
        float ad = sAd[j] * v;
        if (j < 32) { a0s += as; a0d += ad; }
        else        { a1s += as; a1d += ad; }
    }

    g_asrc[n * 2 + 0] = a0s; g_asrc[n * 2 + 1] = a1s;
    g_adst[n * 2 + 0] = a0d; g_adst[n * 2 + 1] = a1d;

    // self-loop contribution (src = dst = n)
    float e0 = a0s + a0d; e0 = e0 > 0.f ? e0 : NEG * e0;
    float e1 = a1s + a1d; e1 = e1 > 0.f ? e1 : NEG * e1;
    float w0 = __expf(e0);
    float w1h = __expf(e1);
    g_denom[n * 2 + 0] = w0;
    g_denom[n * 2 + 1] = w1h;

    // store xp as fp16 (gathered in k2), and fp32 self-loop-weighted num
    union { uint4 u; __half2 h[4]; } pk;
    uint4* xpo  = (uint4*)(g_xp + (size_t)n * 64);
    float4* numo = (float4*)(g_num + (size_t)n * 64);
    #pragma unroll
    for (int q = 0; q < 8; q++) {
        float w = (q < 4) ? w0 : w1h;
        #pragma unroll
        for (int j = 0; j < 4; j++)
            pk.h[j] = __floats2half2_rn(xp[8 * q + 2 * j], xp[8 * q + 2 * j + 1]);
        xpo[q] = pk.u;
        #pragma unroll
        for (int j = 0; j < 2; j++) {
            int base = 8 * q + 4 * j;
            numo[2 * q + j] = make_float4(w * xp[base], w * xp[base + 1],
                                          w * xp[base + 2], w * xp[base + 3]);
        }
    }
}

// K2: per-edge scatter. 8 lanes per edge; each lane handles 8 channels
// (16B fp16 gather + two red.v4 fp32). Softmax max-shift skipped
// (shift-invariant; |e| small so exp cannot overflow).
__global__ void k2_edge_scatter(int E) {
    long long t = (long long)blockIdx.x * blockDim.x + threadIdx.x;
    int e = (int)(t >> 3);
    int q = (int)(t & 7);
    if (e >= E) return;
    int2 sd = __ldg(&g_edge[e]);

    int h = q >> 2;
    float ee = g_asrc[sd.x * 2 + h] + g_adst[sd.y * 2 + h];
    ee = ee > 0.f ? ee : NEG * ee;
    float w = __expf(ee);
    if ((q & 3) == 0) atomicAdd(&g_denom[sd.y * 2 + h], w);

    union { uint4 u; __half2 hh[4]; } v;
    v.u = *((const uint4*)(g_xp + (size_t)sd.x * 64) + q);
    float2 f0 = __half22float2(v.hh[0]);
    float2 f1 = __half22float2(v.hh[1]);
    float2 f2 = __half22float2(v.hh[2]);
    float2 f3 = __half22float2(v.hh[3]);

    float* dst = g_num + (size_t)sd.y * 64 + q * 8;
    red_add_v4(dst,     w * f0.x, w * f0.y, w * f1.x, w * f1.y);
    red_add_v4(dst + 4, w * f2.x, w * f2.y, w * f3.x, w * f3.y);
}

// K3: per-node finalize. Persistent warps; lane c keeps its w1 column (64
// weights) in registers; h broadcast via shfl. No shared-memory traffic.
__global__ void __launch_bounds__(256) k3_node_p(const float* __restrict__ bias,
                                                 const float* __restrict__ w1, int N) {
    int c = threadIdx.x & 31;
    float wt[32], wb[32];
    #pragma unroll
    for (int k = 0; k < 32; k++) {
        wt[k] = __ldg(&w1[k * 32 + c]);
        wb[k] = __ldg(&w1[(32 + k) * 32 + c]);
    }
    float bc = __ldg(&bias[c]);

    int warpId = (blockIdx.x * blockDim.x + threadIdx.x) >> 5;
    int nWarps = (gridDim.x * blockDim.x) >> 5;

    for (int n = warpId; n < N; n += nWarps) {
        float d0 = g_denom[n * 2 + 0] + 1e-16f;
        float d1 = g_denom[n * 2 + 1] + 1e-16f;
        float h = 0.5f * (g_num[(size_t)n * 64 + c] / d0 +
                          g_num[(size_t)n * 64 + 32 + c] / d1) + bc;

        float ps = 0.f, pd = 0.f;
        #pragma unroll
        for (int k = 0; k < 32; k++) {
            float hk = __shfl_sync(0xFFFFFFFFu, h, k);
            ps = fmaf(hk, wt[k], ps);
            pd = fmaf(hk, wb[k], pd);
        }
        g_ps[(size_t)n * 32 + c] = __float2half_rn(ps);
        g_pd[(size_t)n * 32 + c] = __float2half_rn(pd);
    }
}

// K4: per-edge MLP. 4 lanes per edge, 8 hidden units per lane; fp16 gathers.
// hidden = relu(ps[s] + pd[d] + b1); logit = hidden . w2 + b2; * (1/TEMP).
__global__ void k4_edge_mlp(const float* __restrict__ b1, const float* __restrict__ w2,
                            const float* __restrict__ b2, float* __restrict__ out, int E) {
    int tid = blockIdx.x * blockDim.x + threadIdx.x;
    int q = tid & 3;
    float b1r[8], w2r[8];
    #pragma unroll
    for (int i = 0; i < 8; i++) {
        b1r[i] = __ldg(&b1[q * 8 + i]);
        w2r[i] = __ldg(&w2[q * 8 + i]);
    }
    float b2v = __ldg(&b2[0]);
    int step = (gridDim.x * blockDim.x) >> 2;

    for (int e = tid >> 2; e < E; e += step) {
        int2 sd = __ldg(&g_edge[e]);
        union { uint4 u; __half2 hh[4]; } a, b;
        a.u = *((const uint4*)(g_ps + (size_t)sd.x * 32) + q);
        b.u = *((const uint4*)(g_pd + (size_t)sd.y * 32) + q);

        float acc = 0.f;
        #pragma unroll
        for (int j = 0; j < 4; j++) {
            float2 fa = __half22float2(a.hh[j]);
            float2 fb = __half22float2(b.hh[j]);
            float h0 = fmaxf(fa.x + fb.x + b1r[2 * j], 0.f);
            float h1 = fmaxf(fa.y + fb.y + b1r[2 * j + 1], 0.f);
            acc = fmaf(h0, w2r[2 * j], acc);
            acc = fmaf(h1, w2r[2 * j + 1], acc);
        }
        acc += __shfl_xor_sync(0xFFFFFFFFu, acc, 1);
        acc += __shfl_xor_sync(0xFFFFFFFFu, acc, 2);
        if (q == 0) out[e] = (acc + b2v) * INV_TEMP;
    }
}

extern "C" void kernel_launch(void* const* d_in, const int* in_sizes, int n_in,
                              void* d_out, int out_size) {
    const float* x        = (const float*)d_in[0];
    const void*  ei       = d_in[1];                 // int64 or int32, detected on device
    const float* W        = (const float*)d_in[2];
    const float* att_src  = (const float*)d_in[3];
    const float* att_dst  = (const float*)d_in[4];
    const float* bias     = (const float*)d_in[5];
    const float* w1       = (const float*)d_in[6];
    const float* b1       = (const float*)d_in[7];
    const float* w2       = (const float*)d_in[8];
    const float* b2       = (const float*)d_in[9];
    float* out = (float*)d_out;

    int N = in_sizes[0] / 16;  // x is [N, 16]
    int E = in_sizes[1] / 2;   // edge_index is [2, E]

    k0_detect<<<1, 32>>>((const int*)ei);
    k0_pack<<<(E + 255) / 256, 256>>>(ei, E);
    k1_node<<<(N + 127) / 128, 128>>>(x, W, att_src, att_dst, N);
    {
        long long T = (long long)E * 8;
        k2_edge_scatter<<<(unsigned)((T + 255) / 256), 256>>>(E);
    }
    k3_node_p<<<592, 256>>>(bias, w1, N);       // 148 SMs * 4 blocks, persistent warps
    k4_edge_mlp<<<1184, 256>>>(b1, w2, b2, out, E);
}

// round 3
// speedup vs baseline: 1.5639x; 1.2935x over previous
#include <cuda_runtime.h>
#include <cuda_fp16.h>

// Problem constants: N=100000, E=1600000, IN_C=16, HID=32, HEADS=2
#define MAXN 100000
#define MAXE 1600000
#define NEG 0.2f
#define INV_TEMP (1.0f / 0.7f)

// ---- device scratch (static; no allocations allowed) ----
__device__ __align__(16) __half g_xp[MAXN * 64];   // [N][64] projected features (fp16)
__device__ float g_asrc[MAXN * 2];                 // attention src logits per head
__device__ float g_adst[MAXN * 2];                 // attention dst logits per head
__device__ __align__(16) __half g_h[MAXN * 32];    // node embedding after GAT (fp16)
__device__ __align__(16) __half g_ps[MAXN * 32];   // h @ w1[0:32,:]  (fp16)
__device__ __align__(16) __half g_pd[MAXN * 32];   // h @ w1[32:64,:] (fp16)
__device__ __align__(16) int2 g_edge[MAXE];        // packed (src, dst)
__device__ int g_srcs[MAXE];                       // CSR: src ids grouped by dst
__device__ int g_deg[MAXN];                        // in-degree histogram
__device__ int g_off[MAXN + 1];                    // CSR offsets
__device__ int g_cur[MAXN];                        // scatter cursors
__device__ int g_bsum[128];                        // scan block sums
__device__ int g_is64;

// K0a: zero the degree histogram
__global__ void k_zero(int N) {
    int i = blockIdx.x * blockDim.x + threadIdx.x;
    if (i < N) g_deg[i] = 0;
}

// K0b: detect int64 vs int32 edge_index storage
__global__ void k0_detect(const int* ei_words) {
    if (threadIdx.x == 0 && blockIdx.x == 0) {
        int nonzero = 0;
        #pragma unroll
        for (int i = 0; i < 64; i++)
            if (ei_words[2 * i + 1] != 0) nonzero++;
        g_is64 = (nonzero == 0) ? 1 : 0;
    }
}

// K0c: pack edges to int2 and build in-degree histogram
__global__ void k0_pack(const void* __restrict__ ei, int E) {
    int e = blockIdx.x * blockDim.x + threadIdx.x;
    if (e >= E) return;
    int s, d;
    if (g_is64) {
        const long long* p = (const long long*)ei;
        s = (int)p[e];
        d = (int)p[e + E];
    } else {
        const int* p = (const int*)ei;
        s = p[e];
        d = p[e + E];
    }
    g_edge[e] = make_int2(s, d);
    atomicAdd(&g_deg[d], 1);
}

// Scan stage 1: per-block (1024) exclusive scan of g_deg -> g_off, block sums
__global__ void k_scan1(int N) {
    __shared__ int sh[1024];
    int tid = threadIdx.x;
    int i = blockIdx.x * 1024 + tid;
    int v = (i < N) ? g_deg[i] : 0;
    sh[tid] = v;
    __syncthreads();
    #pragma unroll
    for (int ofs = 1; ofs < 1024; ofs <<= 1) {
        int t = (tid >= ofs) ? sh[tid - ofs] : 0;
        __syncthreads();
        sh[tid] += t;
        __syncthreads();
    }
    if (i < N) g_off[i] = sh[tid] - v;      // exclusive within block
    if (tid == 1023) g_bsum[blockIdx.x] = sh[1023];
}

// Scan stage 2: exclusive scan of block sums (<=98 blocks) in one block
__global__ void k_scan2(int NB) {
    __shared__ int sh[128];
    int t = threadIdx.x;
    int v = (t < NB) ? g_bsum[t] : 0;
    sh[t] = v;
    __syncthreads();
    #pragma unroll
    for (int ofs = 1; ofs < 128; ofs <<= 1) {
        int tv = (t >= ofs) ? sh[t - ofs] : 0;
        __syncthreads();
        sh[t] += tv;
        __syncthreads();
    }
    if (t < NB) g_bsum[t] = sh[t] - v;
}

// Scan stage 3: add block bases; init cursors; set sentinel
__global__ void k_scan3(int N, int E) {
    int i = blockIdx.x * blockDim.x + threadIdx.x;
    if (i < N) {
        int o = g_off[i] + g_bsum[i >> 10];
        g_off[i] = o;
        g_cur[i] = o;
    }
    if (i == 0) g_off[N] = E;
}

// Scatter edges into dst-grouped CSR
__global__ void k_scatter(int E) {
    int e = blockIdx.x * blockDim.x + threadIdx.x;
    if (e >= E) return;
    int2 sd = g_edge[e];
    int pos = atomicAdd(&g_cur[sd.y], 1);
    g_srcs[pos] = sd.x;
}

// K1: per-node: xp = x@W (fp16 store), attention logits
__global__ void k1_node(const float* __restrict__ x, const float* __restrict__ W,
                        const float* __restrict__ att_src, const float* __restrict__ att_dst,
                        int N) {
    __shared__ float sW[16 * 64];
    __shared__ float sAs[64];
    __shared__ float sAd[64];
    int tid = threadIdx.x;
    for (int i = tid; i < 16 * 64; i += blockDim.x) sW[i] = W[i];
    if (tid < 64) { sAs[tid] = att_src[tid]; sAd[tid] = att_dst[tid]; }
    __syncthreads();

    int n = blockIdx.x * blockDim.x + tid;
    if (n >= N) return;

    float xv[16];
    const float4* x4 = (const float4*)(x + (size_t)n * 16);
    #pragma unroll
    for (int i = 0; i < 4; i++) {
        float4 t = x4[i];
        xv[4 * i + 0] = t.x; xv[4 * i + 1] = t.y;
        xv[4 * i + 2] = t.z; xv[4 * i + 3] = t.w;
    }

    float xp[64];
    float a0s = 0.f, a1s = 0.f, a0d = 0.f, a1d = 0.f;
    #pragma unroll
    for (int j = 0; j < 64; j++) {
        float v = 0.f;
        #pragma unroll
        for (int k = 0; k < 16; k++) v = fmaf(xv[k], sW[k * 64 + j], v);
        xp[j] = v;
        float as = sAs[j] * v;
        float ad = sAd[j] * v;
        if (j < 32) { a0s += as; a0d += ad; }
        else        { a1s += as; a1d += ad; }
    }

    g_asrc[n * 2 + 0] = a0s; g_asrc[n * 2 + 1] = a1s;
    g_adst[n * 2 + 0] = a0d; g_adst[n * 2 + 1] = a1d;

    union { uint4 u; __half2 h[4]; } pk;
    uint4* xpo = (uint4*)(g_xp + (size_t)n * 64);
    #pragma unroll
    for (int q = 0; q < 8; q++) {
        #pragma unroll
        for (int j = 0; j < 4; j++)
            pk.h[j] = __floats2half2_rn(xp[8 * q + 2 * j], xp[8 * q + 2 * j + 1]);
        xpo[q] = pk.u;
    }
}

// K2b: warp-per-destination-node GAT aggregation from CSR. Lane c owns
// channels {2c, 2c+1} (head = c/16). Accumulators and denominator live in
// registers; unroll-4 prefetch batches the gathers. Softmax max-shift
// skipped (shift-invariant, |e| small).
__global__ void __launch_bounds__(256) k2b_aggregate(const float* __restrict__ bias, int N) {
    int n = (blockIdx.x * blockDim.x + threadIdx.x) >> 5;
    if (n >= N) return;
    int c = threadIdx.x & 31;
    int h = c >> 4;

    float adn = g_adst[n * 2 + h];
    // self-loop init
    float ee = g_asrc[n * 2 + h] + adn;
    ee = ee > 0.f ? ee : NEG * ee;
    float w = __expf(ee);
    float2 xs = __half22float2(*(const __half2*)(g_xp + (size_t)n * 64 + 2 * c));
    float acc0 = w * xs.x, acc1 = w * xs.y, dsum = w;

    int i = g_off[n];
    int end = g_off[n + 1];

    for (; i + 4 <= end; i += 4) {
        int s0 = g_srcs[i], s1 = g_srcs[i + 1], s2 = g_srcs[i + 2], s3 = g_srcs[i + 3];
        float a0 = g_asrc[s0 * 2 + h];
        float a1 = g_asrc[s1 * 2 + h];
        float a2 = g_asrc[s2 * 2 + h];
        float a3 = g_asrc[s3 * 2 + h];
        __half2 x0 = *(const __half2*)(g_xp + (size_t)s0 * 64 + 2 * c);
        __half2 x1 = *(const __half2*)(g_xp + (size_t)s1 * 64 + 2 * c);
        __half2 x2 = *(const __half2*)(g_xp + (size_t)s2 * 64 + 2 * c);
        __half2 x3 = *(const __half2*)(g_xp + (size_t)s3 * 64 + 2 * c);

        float e0 = a0 + adn; e0 = e0 > 0.f ? e0 : NEG * e0;
        float e1 = a1 + adn; e1 = e1 > 0.f ? e1 : NEG * e1;
        float e2 = a2 + adn; e2 = e2 > 0.f ? e2 : NEG * e2;
        float e3 = a3 + adn; e3 = e3 > 0.f ? e3 : NEG * e3;
        float w0 = __expf(e0), w1 = __expf(e1), w2 = __expf(e2), w3 = __expf(e3);
        dsum += (w0 + w1) + (w2 + w3);

        float2 f0 = __half22float2(x0);
        float2 f1 = __half22float2(x1);
        float2 f2 = __half22float2(x2);
        float2 f3 = __half22float2(x3);
        acc0 = fmaf(w0, f0.x, acc0); acc1 = fmaf(w0, f0.y, acc1);
        acc0 = fmaf(w1, f1.x, acc0); acc1 = fmaf(w1, f1.y, acc1);
        acc0 = fmaf(w2, f2.x, acc0); acc1 = fmaf(w2, f2.y, acc1);
        acc0 = fmaf(w3, f3.x, acc0); acc1 = fmaf(w3, f3.y, acc1);
    }
    for (; i < end; i++) {
        int s = g_srcs[i];
        float a = g_asrc[s * 2 + h];
        __half2 xh = *(const __half2*)(g_xp + (size_t)s * 64 + 2 * c);
        float e0 = a + adn; e0 = e0 > 0.f ? e0 : NEG * e0;
        float w0 = __expf(e0);
        dsum += w0;
        float2 f = __half22float2(xh);
        acc0 = fmaf(w0, f.x, acc0);
        acc1 = fmaf(w0, f.y, acc1);
    }

    float d0 = __shfl_sync(0xFFFFFFFFu, dsum, 0);
    float d1 = __shfl_sync(0xFFFFFFFFu, dsum, 16);
    float p0 = __shfl_sync(0xFFFFFFFFu, acc0, (c + 16) & 31);
    float p1 = __shfl_sync(0xFFFFFFFFu, acc1, (c + 16) & 31);

    if (c < 16) {
        // lane c holds head0 channels {2c,2c+1}; lane c+16 holds head1 same channels
        float h0 = 0.5f * (acc0 / d0 + p0 / d1) + bias[2 * c];
        float h1 = 0.5f * (acc1 / d0 + p1 / d1) + bias[2 * c + 1];
        *(__half2*)(g_h + (size_t)n * 32 + 2 * c) = __floats2half2_rn(h0, h1);
    }
}

// K3: fold MLP layer-1 into per-node partials. Persistent warps; lane c keeps
// its w1 column (64 weights) in registers; h broadcast via shfl.
__global__ void __launch_bounds__(256) k3_node_p(const float* __restrict__ w1, int N) {
    int c = threadIdx.x & 31;
    float wt[32], wb[32];
    #pragma unroll
    for (int k = 0; k < 32; k++) {
        wt[k] = __ldg(&w1[k * 32 + c]);
        wb[k] = __ldg(&w1[(32 + k) * 32 + c]);
    }

    int warpId = (blockIdx.x * blockDim.x + threadIdx.x) >> 5;
    int nWarps = (gridDim.x * blockDim.x) >> 5;

    for (int n = warpId; n < N; n += nWarps) {
        float h = __half2float(g_h[(size_t)n * 32 + c]);
        float ps = 0.f, pd = 0.f;
        #pragma unroll
        for (int k = 0; k < 32; k++) {
            float hk = __shfl_sync(0xFFFFFFFFu, h, k);
            ps = fmaf(hk, wt[k], ps);
            pd = fmaf(hk, wb[k], pd);
        }
        g_ps[(size_t)n * 32 + c] = __float2half_rn(ps);
        g_pd[(size_t)n * 32 + c] = __float2half_rn(pd);
    }
}

// K4: per-edge MLP. 4 lanes per edge, 8 hidden units per lane; fp16 gathers.
__global__ void k4_edge_mlp(const float* __restrict__ b1, const float* __restrict__ w2,
                            const float* __restrict__ b2, float* __restrict__ out, int E) {
    int tid = blockIdx.x * blockDim.x + threadIdx.x;
    int q = tid & 3;
    float b1r[8], w2r[8];
    #pragma unroll
    for (int i = 0; i < 8; i++) {
        b1r[i] = __ldg(&b1[q * 8 + i]);
        w2r[i] = __ldg(&w2[q * 8 + i]);
    }
    float b2v = __ldg(&b2[0]);
    int step = (gridDim.x * blockDim.x) >> 2;

    for (int e = tid >> 2; e < E; e += step) {
        int2 sd = __ldg(&g_edge[e]);
        union { uint4 u; __half2 hh[4]; } a, b;
        a.u = *((const uint4*)(g_ps + (size_t)sd.x * 32) + q);
        b.u = *((const uint4*)(g_pd + (size_t)sd.y * 32) + q);

        float acc = 0.f;
        #pragma unroll
        for (int j = 0; j < 4; j++) {
            float2 fa = __half22float2(a.hh[j]);
            float2 fb = __half22float2(b.hh[j]);
            float h0 = fmaxf(fa.x + fb.x + b1r[2 * j], 0.f);
            float h1 = fmaxf(fa.y + fb.y + b1r[2 * j + 1], 0.f);
            acc = fmaf(h0, w2r[2 * j], acc);
            acc = fmaf(h1, w2r[2 * j + 1], acc);
        }
        acc += __shfl_xor_sync(0xFFFFFFFFu, acc, 1);
        acc += __shfl_xor_sync(0xFFFFFFFFu, acc, 2);
        if (q == 0) out[e] = (acc + b2v) * INV_TEMP;
    }
}

extern "C" void kernel_launch(void* const* d_in, const int* in_sizes, int n_in,
                              void* d_out, int out_size) {
    const float* x        = (const float*)d_in[0];
    const void*  ei       = d_in[1];
    const float* W        = (const float*)d_in[2];
    const float* att_src  = (const float*)d_in[3];
    const float* att_dst  = (const float*)d_in[4];
    const float* bias     = (const float*)d_in[5];
    const float* w1       = (const float*)d_in[6];
    const float* b1       = (const float*)d_in[7];
    const float* w2       = (const float*)d_in[8];
    const float* b2       = (const float*)d_in[9];
    float* out = (float*)d_out;

    int N = in_sizes[0] / 16;  // x is [N, 16]
    int E = in_sizes[1] / 2;   // edge_index is [2, E]
    int NB = (N + 1023) / 1024;

    k_zero<<<(N + 255) / 256, 256>>>(N);
    k0_detect<<<1, 32>>>((const int*)ei);
    k0_pack<<<(E + 255) / 256, 256>>>(ei, E);
    k_scan1<<<NB, 1024>>>(N);
    k_scan2<<<1, 128>>>(NB);
    k_scan3<<<NB, 1024>>>(N, E);
    k_scatter<<<(E + 255) / 256, 256>>>(E);
    k1_node<<<(N + 127) / 128, 128>>>(x, W, att_src, att_dst, N);
    {
        long long T = (long long)N * 32;
        k2b_aggregate<<<(unsigned)((T + 255) / 256), 256>>>(bias, N);
    }
    k3_node_p<<<592, 256>>>(w1, N);
    k4_edge_mlp<<<1184, 256>>>(b1, w2, b2, out, E);
}